// round 13
// baseline (speedup 1.0000x reference)
#include <cuda_runtime.h>
#include <cuda_fp16.h>
#include <cstdint>

#define N_NODES 50000
#define N_EDGES 1600000
#define IN_DIM  1024
#define MID_DIM 256
#define NBLK_SCAN ((N_NODES + 255) / 256)   // 196

// ---------------- scratch (device globals; no allocs allowed) ----------------
__device__ __align__(16) float  g_dis[N_NODES];
__device__ __align__(16) __half g_xh  [(size_t)N_NODES * IN_DIM];   // fp16(x)
__device__ __align__(16) __half g_w1h [(size_t)IN_DIM * MID_DIM];   // fp16(W1)
__device__ __align__(16) __half g_w2h [(size_t)MID_DIM * IN_DIM];   // fp16(W2)
__device__ __align__(16) __half g_xw  [(size_t)N_NODES * MID_DIM];  // x@W1
__device__ __align__(16) __half g_h   [(size_t)N_NODES * MID_DIM];  // relu(A xw + b1)
__device__ __align__(16) __half g_ag2 [(size_t)N_NODES * MID_DIM];  // A h
__device__ int    g_cnt[N_NODES];
__device__ int    g_rowptr[N_NODES];
__device__ int    g_cur[N_NODES];
__device__ int    g_bsum[NBLK_SCAN];
__device__ __align__(8) float2 g_epack[N_EDGES];  // {src_as_float_bits, norm}
__device__ int    g_is64;

// ---------------- helpers ----------------
__device__ __forceinline__ uint32_t smem_u32(const void* p) {
    uint32_t a;
    asm("{ .reg .u64 t; cvta.to.shared.u64 t, %1; cvt.u32.u64 %0, t; }"
        : "=r"(a) : "l"(p));
    return a;
}
__device__ __forceinline__ void ldmatrix_x4(uint32_t* r, uint32_t addr) {
    asm volatile("ldmatrix.sync.aligned.m8n8.x4.shared.b16 {%0,%1,%2,%3}, [%4];"
                 : "=r"(r[0]), "=r"(r[1]), "=r"(r[2]), "=r"(r[3]) : "r"(addr));
}
__device__ __forceinline__ void ldmatrix_x2t(uint32_t* r, uint32_t addr) {
    asm volatile("ldmatrix.sync.aligned.m8n8.x2.trans.shared.b16 {%0,%1}, [%2];"
                 : "=r"(r[0]), "=r"(r[1]) : "r"(addr));
}
__device__ __forceinline__ void mma_f16(float* c, const uint32_t* a, const uint32_t* b) {
    asm volatile(
        "mma.sync.aligned.m16n8k16.row.col.f32.f16.f16.f32 "
        "{%0,%1,%2,%3}, {%4,%5,%6,%7}, {%8,%9}, {%0,%1,%2,%3};"
        : "+f"(c[0]), "+f"(c[1]), "+f"(c[2]), "+f"(c[3])
        : "r"(a[0]), "r"(a[1]), "r"(a[2]), "r"(a[3]), "r"(b[0]), "r"(b[1]));
}
__device__ __forceinline__ void cp_async16(uint32_t dst, const void* src) {
    asm volatile("cp.async.ca.shared.global [%0], [%1], 16;"
                 :: "r"(dst), "l"(src));
}
__device__ __forceinline__ void cp_async16p(uint32_t dst, const void* src, int nbytes) {
    asm volatile("cp.async.ca.shared.global [%0], [%1], 16, %2;"
                 :: "r"(dst), "l"(src), "r"(nbytes));
}
__device__ __forceinline__ void cp_commit() {
    asm volatile("cp.async.commit_group;");
}
__device__ __forceinline__ void cp_wait1() {
    asm volatile("cp.async.wait_group 1;");
}

// ---------------- fp32 -> fp16 conversion (8 elts/thread) ----------------
__global__ void conv_half_kernel(const float4* __restrict__ src,
                                 uint4* __restrict__ dst, int n8) {
    int i = blockIdx.x * blockDim.x + threadIdx.x;
    if (i >= n8) return;
    float4 a = __ldg(src + 2 * i);
    float4 b = __ldg(src + 2 * i + 1);
    uint4 o;
    ((__half2*)&o)[0] = __floats2half2_rn(a.x, a.y);
    ((__half2*)&o)[1] = __floats2half2_rn(a.z, a.w);
    ((__half2*)&o)[2] = __floats2half2_rn(b.x, b.y);
    ((__half2*)&o)[3] = __floats2half2_rn(b.z, b.w);
    dst[i] = o;
}

// ---------------- edge-index dtype detection ----------------
__global__ void detect_kernel(const int* __restrict__ ei_words) {
    if (threadIdx.x == 0 && blockIdx.x == 0) {
        int is64 = 1;
        #pragma unroll 1
        for (int i = 1; i < 512; i += 2)
            if (ei_words[i] != 0) { is64 = 0; break; }
        g_is64 = is64;
    }
}
__device__ __forceinline__ int edge_node(const void* ei, long long idx, int is64) {
    if (is64) return (int)((const long long*)ei)[idx];
    return ((const int*)ei)[idx];
}

// ---------------- CSR build ----------------
__global__ void zero_cnt_kernel() {
    int i = blockIdx.x * blockDim.x + threadIdx.x;
    if (i < N_NODES) g_cnt[i] = 0;
}
__global__ void hist_kernel(const void* __restrict__ ei) {
    int e = blockIdx.x * blockDim.x + threadIdx.x;
    if (e >= N_EDGES) return;
    int d = edge_node(ei, (long long)e + N_EDGES, g_is64);
    atomicAdd(&g_cnt[d], 1);
}
__global__ void dis_kernel() {
    int i = blockIdx.x * blockDim.x + threadIdx.x;
    if (i < N_NODES) g_dis[i] = rsqrtf((float)(g_cnt[i] + 1));
}
__global__ void scan1_kernel() {
    __shared__ int sh[256];
    int i = blockIdx.x * 256 + threadIdx.x;
    int v = (i < N_NODES) ? g_cnt[i] : 0;
    sh[threadIdx.x] = v;
    __syncthreads();
    #pragma unroll
    for (int off = 1; off < 256; off <<= 1) {
        int t = (threadIdx.x >= off) ? sh[threadIdx.x - off] : 0;
        __syncthreads();
        sh[threadIdx.x] += t;
        __syncthreads();
    }
    if (i < N_NODES) g_rowptr[i] = sh[threadIdx.x];
    if (threadIdx.x == 255) g_bsum[blockIdx.x] = sh[255];
}
__global__ void scan2_kernel() {
    __shared__ int sh[256];
    int v = (threadIdx.x < NBLK_SCAN) ? g_bsum[threadIdx.x] : 0;
    sh[threadIdx.x] = v;
    __syncthreads();
    #pragma unroll
    for (int off = 1; off < 256; off <<= 1) {
        int t = (threadIdx.x >= off) ? sh[threadIdx.x - off] : 0;
        __syncthreads();
        sh[threadIdx.x] += t;
        __syncthreads();
    }
    if (threadIdx.x < NBLK_SCAN) g_bsum[threadIdx.x] = sh[threadIdx.x] - v;
}
__global__ void scan3_kernel() {
    int i = blockIdx.x * 256 + threadIdx.x;
    if (i < N_NODES) {
        int ex = g_rowptr[i] - g_cnt[i] + g_bsum[blockIdx.x];
        g_rowptr[i] = ex;
        g_cur[i] = ex;
    }
}
__global__ void scatter_kernel(const void* __restrict__ ei) {
    int e = blockIdx.x * blockDim.x + threadIdx.x;
    if (e >= N_EDGES) return;
    int is64 = g_is64;
    int s = edge_node(ei, e, is64);
    int d = edge_node(ei, (long long)e + N_EDGES, is64);
    int pos = atomicAdd(&g_cur[d], 1);
    g_epack[pos] = make_float2(__int_as_float(s), g_dis[s] * g_dis[d]);
}

// ---------------- fp16 mma.sync GEMM, BM=128 BN=256 BK=32, cp.async 3-stage ----------------
// 8 warps as 2(m) x 4(n); 64x64 per warp; 2 k-steps (k16) per tile -> one barrier per 32 K.
// Dynamic SMEM: As 3x[128][40] halves (stride 80B), Bs 3x[32][264] halves (stride 528B).
// Both strides 16B-aligned; ldmatrix phases conflict-free (r*80 mod 128 and r*16 mod 128 distinct).
#define A_STRIDE 40
#define B_STRIDE 264
#define A_STAGE_B (128 * A_STRIDE * 2)          // 10240
#define B_STAGE_B (32 * B_STRIDE * 2)           // 16896
#define GEMM_SMEM (3 * A_STAGE_B + 3 * B_STAGE_B)  // 81408

template <bool USE_BIAS, bool OUT_HALF>
__global__ __launch_bounds__(256) void gemm_f16_kernel(
    const __half* __restrict__ A, const __half* __restrict__ B,
    const float* __restrict__ bias, void* __restrict__ Cv,
    int M, int N, int K)
{
    extern __shared__ __align__(16) char smem[];
    const uint32_t as_base = smem_u32(smem);                    // 3 A stages
    const uint32_t bs_base = as_base + 3 * A_STAGE_B;           // 3 B stages

    const int tid  = threadIdx.x;
    const int wid  = tid >> 5;
    const int lane = tid & 31;
    const int warp_m = wid & 1;
    const int warp_n = wid >> 1;         // 0..3
    const int rowBase = blockIdx.y * 128;
    const int colBase = blockIdx.x * 256;
    const int KT = K / 32;

    // ----- A staging: 2 chunks/thread (c = tid, tid+256); row=c>>2, colh=(c&3)*8 -----
    const int ar0 = tid >> 2,          ac0 = (tid & 3) * 8;
    const int ar1 = (tid + 256) >> 2,  ac1 = ((tid + 256) & 3) * 8;
    const bool a_ok0 = (rowBase + ar0 < M);
    const bool a_ok1 = (rowBase + ar1 < M);
    const __half* a_src0 = A + (size_t)(a_ok0 ? rowBase + ar0 : 0) * K + ac0;
    const __half* a_src1 = A + (size_t)(a_ok1 ? rowBase + ar1 : 0) * K + ac1;
    const uint32_t a_dst0 = as_base + (uint32_t)((ar0 * A_STRIDE + ac0) * 2);
    const uint32_t a_dst1 = as_base + (uint32_t)((ar1 * A_STRIDE + ac1) * 2);

    // ----- B staging: 4 chunks/thread (c = tid + 256j); row=c>>5, colh=(c&31)*8 -----
    uint32_t b_dst[4];
    const __half* b_src[4];
    #pragma unroll
    for (int j = 0; j < 4; j++) {
        int c = tid + 256 * j;
        int br = c >> 5, bc = (c & 31) * 8;
        b_dst[j] = bs_base + (uint32_t)((br * B_STRIDE + bc) * 2);
        b_src[j] = B + (size_t)br * N + colBase + bc;
    }

    auto issue_stage = [&](int s, int t) {
        cp_async16p(a_dst0 + s * A_STAGE_B, a_src0 + t * 32, a_ok0 ? 16 : 0);
        cp_async16p(a_dst1 + s * A_STAGE_B, a_src1 + t * 32, a_ok1 ? 16 : 0);
        #pragma unroll
        for (int j = 0; j < 4; j++)
            cp_async16(b_dst[j] + s * B_STAGE_B, b_src[j] + (size_t)t * 32 * N);
    };

    float acc[4][8][4];
    #pragma unroll
    for (int i = 0; i < 4; i++)
        #pragma unroll
        for (int j = 0; j < 8; j++)
            #pragma unroll
            for (int r = 0; r < 4; r++) acc[i][j][r] = 0.f;

    // fragment ldmatrix base addresses
    uint32_t a_off[4], b_off[8];
    {
        const int arow = lane & 15;
        const int acol = (lane >> 4) * 8;
        #pragma unroll
        for (int i = 0; i < 4; i++)
            a_off[i] = as_base + (uint32_t)(((warp_m * 64 + i * 16 + arow) * A_STRIDE + acol) * 2);
        #pragma unroll
        for (int j = 0; j < 8; j++)
            b_off[j] = bs_base + (uint32_t)(((lane & 15) * B_STRIDE + warp_n * 64 + j * 8) * 2);
    }

    // prologue: 2 stages in flight
    issue_stage(0, 0); cp_commit();
    if (KT > 1) { issue_stage(1, 1); } cp_commit();

    int sbuf = 0;
    for (int t = 0; t < KT; t++) {
        cp_wait1();
        __syncthreads();
        // issue stage t+2 into buffer (t+2)%3 (distinct from t and t+1)
        if (t + 2 < KT) {
            int s2 = sbuf + 2; if (s2 >= 3) s2 -= 3;
            issue_stage(s2, t + 2);
        }
        cp_commit();

        const uint32_t abase = a_off[0] + 0;  // (kept for clarity)
        #pragma unroll
        for (int ks = 0; ks < 2; ks++) {
            const uint32_t akoff = sbuf * A_STAGE_B + ks * 16 * 2;          // +16 halves along row
            const uint32_t bkoff = sbuf * B_STAGE_B + ks * 16 * B_STRIDE * 2; // +16 rows
            uint32_t af[4][4];
            #pragma unroll
            for (int i = 0; i < 4; i++) ldmatrix_x4(af[i], a_off[i] + akoff);
            #pragma unroll
            for (int jb = 0; jb < 2; jb++) {
                uint32_t bf[4][2];
                #pragma unroll
                for (int jj = 0; jj < 4; jj++)
                    ldmatrix_x2t(bf[jj], b_off[jb * 4 + jj] + bkoff);
                #pragma unroll
                for (int i = 0; i < 4; i++)
                    #pragma unroll
                    for (int jj = 0; jj < 4; jj++)
                        mma_f16(acc[i][jb * 4 + jj], af[i], bf[jj]);
            }
        }
        (void)abase;
        if (++sbuf == 3) sbuf = 0;
    }

    const int lg = lane >> 2;
    const int lr = lane & 3;
    #pragma unroll
    for (int i = 0; i < 4; i++) {
        const int r0 = rowBase + warp_m * 64 + i * 16 + lg;
        #pragma unroll
        for (int half = 0; half < 2; half++) {
            const int rr = r0 + half * 8;
            if (rr >= M) continue;
            #pragma unroll
            for (int j = 0; j < 8; j++) {
                const int cc = colBase + warp_n * 64 + j * 8 + lr * 2;
                float v0 = acc[i][j][half * 2 + 0];
                float v1 = acc[i][j][half * 2 + 1];
                if (USE_BIAS) { v0 += bias[cc]; v1 += bias[cc + 1]; }
                if (OUT_HALF) {
                    __half2* C = (__half2*)Cv;
                    C[((size_t)rr * N + cc) >> 1] = __floats2half2_rn(v0, v1);
                } else {
                    float* C = (float*)Cv;
                    *(float2*)(C + (size_t)rr * N + cc) = make_float2(v0, v1);
                }
            }
        }
    }
}

// ---------------- CSR gather aggregation (fp16 in, fp32 accumulate, fp16 out) ----------------
template <bool L1>
__global__ __launch_bounds__(256) void gather_kernel(
    const __half* __restrict__ srcfeat,
    const float* __restrict__ bias,
    __half* __restrict__ out)
{
    __shared__ float2 se[8][32];
    const int w    = threadIdx.x >> 5;
    const int warp = blockIdx.x * 8 + w;
    const int lane = threadIdx.x & 31;
    if (warp >= N_NODES) return;

    const int start = g_rowptr[warp];
    const int end   = start + g_cnt[warp];
    const float di  = g_dis[warp];
    const float nn  = di * di;

    float acc[8];

    // self term
    {
        uint4 raw = __ldg((const uint4*)(srcfeat + (size_t)warp * MID_DIM) + lane);
        const __half2* hp = (const __half2*)&raw;
        #pragma unroll
        for (int q = 0; q < 4; q++) {
            float2 f = __half22float2(hp[q]);
            acc[2 * q]     = f.x * nn;
            acc[2 * q + 1] = f.y * nn;
        }
    }

    // edges: stage 32 records in smem, LDS broadcast per edge
    for (int base = start; base < end; base += 32) {
        const int rem = min(32, end - base);
        if (base + lane < end) se[w][lane] = __ldg(&g_epack[base + lane]);
        __syncwarp();
        #pragma unroll 4
        for (int j = 0; j < rem; j++) {
            const float2 e = se[w][j];
            const int   s  = __float_as_int(e.x);
            const float wt = e.y;
            uint4 raw = __ldg((const uint4*)(srcfeat + (size_t)s * MID_DIM) + lane);
            const __half2* hp = (const __half2*)&raw;
            #pragma unroll
            for (int q = 0; q < 4; q++) {
                float2 f = __half22float2(hp[q]);
                acc[2 * q]     = fmaf(wt, f.x, acc[2 * q]);
                acc[2 * q + 1] = fmaf(wt, f.y, acc[2 * q + 1]);
            }
        }
        __syncwarp();
    }

    uint4 outv;
    __half2* op = (__half2*)&outv;
    if (L1) {
        const int c8 = lane * 8;
        float4 bb0 = *(const float4*)(bias + c8);
        float4 bb1 = *(const float4*)(bias + c8 + 4);
        float b[8] = {bb0.x, bb0.y, bb0.z, bb0.w, bb1.x, bb1.y, bb1.z, bb1.w};
        #pragma unroll
        for (int q = 0; q < 4; q++) {
            float v0 = fmaxf(acc[2 * q]     + b[2 * q],     0.f);
            float v1 = fmaxf(acc[2 * q + 1] + b[2 * q + 1], 0.f);
            op[q] = __floats2half2_rn(v0, v1);
        }
    } else {
        #pragma unroll
        for (int q = 0; q < 4; q++)
            op[q] = __floats2half2_rn(acc[2 * q], acc[2 * q + 1]);
    }
    ((uint4*)(out + (size_t)warp * MID_DIM))[lane] = outv;
}

// ---------------- launch ----------------
extern "C" void kernel_launch(void* const* d_in, const int* in_sizes, int n_in,
                              void* d_out, int out_size)
{
    const float* x  = (const float*)d_in[0];
    const void*  ei = d_in[1];
    const float* W1 = (const float*)d_in[2];
    const float* b1 = (const float*)d_in[3];
    const float* W2 = (const float*)d_in[4];
    const float* b2 = (const float*)d_in[5];
    float* out = (float*)d_out;

    __half *xh, *w1h, *w2h, *xw, *h, *ag2;
    cudaGetSymbolAddress((void**)&xh,  g_xh);
    cudaGetSymbolAddress((void**)&w1h, g_w1h);
    cudaGetSymbolAddress((void**)&w2h, g_w2h);
    cudaGetSymbolAddress((void**)&xw,  g_xw);
    cudaGetSymbolAddress((void**)&h,   g_h);
    cudaGetSymbolAddress((void**)&ag2, g_ag2);

    cudaFuncSetAttribute(gemm_f16_kernel<false, true>,
                         cudaFuncAttributeMaxDynamicSharedMemorySize, GEMM_SMEM);
    cudaFuncSetAttribute(gemm_f16_kernel<true, false>,
                         cudaFuncAttributeMaxDynamicSharedMemorySize, GEMM_SMEM);

    const int nb_nodes = (N_NODES + 255) / 256;
    const int nb_edges = (N_EDGES + 255) / 256;
    const int mblocks = (N_NODES + 127) / 128;
    const int gblocks = (N_NODES + 7) / 8;

    // 1-3: fp16 conversions (W1, W2, x)
    {
        int n8w = (IN_DIM * MID_DIM) / 8;
        conv_half_kernel<<<(n8w + 255) / 256, 256>>>((const float4*)W1, (uint4*)w1h, n8w);
        conv_half_kernel<<<(n8w + 255) / 256, 256>>>((const float4*)W2, (uint4*)w2h, n8w);
        int n8x = (N_NODES * IN_DIM) / 8;
        conv_half_kernel<<<(n8x + 255) / 256, 256>>>((const float4*)x, (uint4*)xh, n8x);
    }

    // 4 (ncu capture slot): GEMM1 xw = x@W1 (fp16 out)
    gemm_f16_kernel<false, true><<<dim3(MID_DIM / 256, mblocks), 256, GEMM_SMEM>>>(
        xh, w1h, nullptr, xw, N_NODES, MID_DIM, IN_DIM);

    // CSR build
    detect_kernel<<<1, 32>>>((const int*)ei);
    zero_cnt_kernel<<<nb_nodes, 256>>>();
    hist_kernel<<<nb_edges, 256>>>(ei);
    dis_kernel<<<nb_nodes, 256>>>();
    scan1_kernel<<<NBLK_SCAN, 256>>>();
    scan2_kernel<<<1, 256>>>();
    scan3_kernel<<<NBLK_SCAN, 256>>>();
    scatter_kernel<<<nb_edges, 256>>>(ei);

    // layer 1 aggregation: h = relu(A_norm xw + b1)
    gather_kernel<true><<<gblocks, 256>>>(xw, b1, h);

    // layer 2: ag2 = A_norm h ; out = ag2@W2 + b2
    gather_kernel<false><<<gblocks, 256>>>(h, nullptr, ag2);
    gemm_f16_kernel<true, false><<<dim3(IN_DIM / 256, mblocks), 256, GEMM_SMEM>>>(
        ag2, w2h, b2, out, N_NODES, IN_DIM, MID_DIM);
}

// round 14
// speedup vs baseline: 1.5046x; 1.5046x over previous
#include <cuda_runtime.h>
#include <cuda_fp16.h>
#include <cstdint>

#define N_NODES 50000
#define N_EDGES 1600000
#define IN_DIM  1024
#define MID_DIM 256
#define NBLK_SCAN ((N_NODES + 255) / 256)   // 196

// ---------------- scratch (device globals; no allocs allowed) ----------------
__device__ __align__(16) float  g_dis[N_NODES];
__device__ __align__(16) __half g_xh  [(size_t)N_NODES * IN_DIM];   // fp16(x)
__device__ __align__(16) __half g_w1h [(size_t)IN_DIM * MID_DIM];   // fp16(W1)
__device__ __align__(16) __half g_w2h [(size_t)MID_DIM * IN_DIM];   // fp16(W2)
__device__ __align__(16) __half g_xw  [(size_t)N_NODES * MID_DIM];  // x@W1
__device__ __align__(16) __half g_h   [(size_t)N_NODES * MID_DIM];  // relu(A xw + b1)
__device__ __align__(16) __half g_ag2 [(size_t)N_NODES * MID_DIM];  // A h
__device__ int    g_cnt[N_NODES];
__device__ int    g_rowptr[N_NODES];
__device__ int    g_cur[N_NODES];
__device__ int    g_bsum[NBLK_SCAN];
__device__ __align__(8) float2 g_epack[N_EDGES];  // {src_as_float_bits, norm}
__device__ int    g_is64;

// ---------------- helpers ----------------
__device__ __forceinline__ uint32_t smem_u32(const void* p) {
    uint32_t a;
    asm("{ .reg .u64 t; cvta.to.shared.u64 t, %1; cvt.u32.u64 %0, t; }"
        : "=r"(a) : "l"(p));
    return a;
}
__device__ __forceinline__ void ldmatrix_x4(uint32_t* r, uint32_t addr) {
    asm volatile("ldmatrix.sync.aligned.m8n8.x4.shared.b16 {%0,%1,%2,%3}, [%4];"
                 : "=r"(r[0]), "=r"(r[1]), "=r"(r[2]), "=r"(r[3]) : "r"(addr));
}
__device__ __forceinline__ void ldmatrix_x2t(uint32_t* r, uint32_t addr) {
    asm volatile("ldmatrix.sync.aligned.m8n8.x2.trans.shared.b16 {%0,%1}, [%2];"
                 : "=r"(r[0]), "=r"(r[1]) : "r"(addr));
}
__device__ __forceinline__ void mma_f16(float* c, const uint32_t* a, const uint32_t* b) {
    asm volatile(
        "mma.sync.aligned.m16n8k16.row.col.f32.f16.f16.f32 "
        "{%0,%1,%2,%3}, {%4,%5,%6,%7}, {%8,%9}, {%0,%1,%2,%3};"
        : "+f"(c[0]), "+f"(c[1]), "+f"(c[2]), "+f"(c[3])
        : "r"(a[0]), "r"(a[1]), "r"(a[2]), "r"(a[3]), "r"(b[0]), "r"(b[1]));
}
__device__ __forceinline__ void cp_async16(uint32_t dst, const void* src, int nbytes) {
    asm volatile("cp.async.ca.shared.global [%0], [%1], 16, %2;"
                 :: "r"(dst), "l"(src), "r"(nbytes));
}
__device__ __forceinline__ void cp_commit() {
    asm volatile("cp.async.commit_group;");
}
__device__ __forceinline__ void cp_wait2() {
    asm volatile("cp.async.wait_group 2;");
}

// ---------------- fp32 -> fp16 conversion (8 elts/thread) ----------------
__global__ void conv_half_kernel(const float4* __restrict__ src,
                                 uint4* __restrict__ dst, int n8) {
    int i = blockIdx.x * blockDim.x + threadIdx.x;
    if (i >= n8) return;
    float4 a = __ldg(src + 2 * i);
    float4 b = __ldg(src + 2 * i + 1);
    uint4 o;
    ((__half2*)&o)[0] = __floats2half2_rn(a.x, a.y);
    ((__half2*)&o)[1] = __floats2half2_rn(a.z, a.w);
    ((__half2*)&o)[2] = __floats2half2_rn(b.x, b.y);
    ((__half2*)&o)[3] = __floats2half2_rn(b.z, b.w);
    dst[i] = o;
}

__device__ __forceinline__ int edge_node(const void* ei, long long idx, int is64) {
    if (is64) return (int)((const long long*)ei)[idx];
    return ((const int*)ei)[idx];
}

// ---------------- CSR build ----------------
// zero counts; block 0 additionally detects the edge-index dtype (int64 vs int32:
// values < 50000 so an int64 layout has all-zero odd 32-bit words)
__global__ void zero_detect_kernel(const int* __restrict__ ei_words) {
    int i = blockIdx.x * blockDim.x + threadIdx.x;
    if (i < N_NODES) g_cnt[i] = 0;
    if (blockIdx.x == 0 && threadIdx.x == 0) {
        int is64 = 1;
        #pragma unroll 1
        for (int k = 1; k < 512; k += 2)
            if (ei_words[k] != 0) { is64 = 0; break; }
        g_is64 = is64;
    }
}
__global__ void hist_kernel(const void* __restrict__ ei) {
    int e = blockIdx.x * blockDim.x + threadIdx.x;
    if (e >= N_EDGES) return;
    int d = edge_node(ei, (long long)e + N_EDGES, g_is64);
    atomicAdd(&g_cnt[d], 1);
}
// blockwise inclusive scan of g_cnt -> g_rowptr, block totals -> g_bsum; also g_dis
__global__ void scan1_kernel() {
    __shared__ int sh[256];
    int i = blockIdx.x * 256 + threadIdx.x;
    int v = (i < N_NODES) ? g_cnt[i] : 0;
    if (i < N_NODES) g_dis[i] = rsqrtf((float)(v + 1));   // +1 self loop
    sh[threadIdx.x] = v;
    __syncthreads();
    #pragma unroll
    for (int off = 1; off < 256; off <<= 1) {
        int t = (threadIdx.x >= off) ? sh[threadIdx.x - off] : 0;
        __syncthreads();
        sh[threadIdx.x] += t;
        __syncthreads();
    }
    if (i < N_NODES) g_rowptr[i] = sh[threadIdx.x];
    if (threadIdx.x == 255) g_bsum[blockIdx.x] = sh[255];
}
__global__ void scan2_kernel() {
    __shared__ int sh[256];
    int v = (threadIdx.x < NBLK_SCAN) ? g_bsum[threadIdx.x] : 0;
    sh[threadIdx.x] = v;
    __syncthreads();
    #pragma unroll
    for (int off = 1; off < 256; off <<= 1) {
        int t = (threadIdx.x >= off) ? sh[threadIdx.x - off] : 0;
        __syncthreads();
        sh[threadIdx.x] += t;
        __syncthreads();
    }
    if (threadIdx.x < NBLK_SCAN) g_bsum[threadIdx.x] = sh[threadIdx.x] - v;
}
__global__ void scan3_kernel() {
    int i = blockIdx.x * 256 + threadIdx.x;
    if (i < N_NODES) {
        int ex = g_rowptr[i] - g_cnt[i] + g_bsum[blockIdx.x];
        g_rowptr[i] = ex;
        g_cur[i] = ex;
    }
}
__global__ void scatter_kernel(const void* __restrict__ ei) {
    int e = blockIdx.x * blockDim.x + threadIdx.x;
    if (e >= N_EDGES) return;
    int is64 = g_is64;
    int s = edge_node(ei, e, is64);
    int d = edge_node(ei, (long long)e + N_EDGES, is64);
    int pos = atomicAdd(&g_cur[d], 1);
    g_epack[pos] = make_float2(__int_as_float(s), g_dis[s] * g_dis[d]);
}

// ---------------- fp16 mma.sync GEMM, BM=128 BN=256 BK=16, cp.async 4-stage ----------------
// (R9 schedule — empirically best: 85us on GEMM1, tensor ~50%.)
// 8 warps as 2(m) x 4(n); 64x64 per warp = 4x8 m16n8k16, acc in 128 regs.
// As stride 24h (48B), Bs stride 264h (528B) — 16B-aligned, conflict-free.
template <bool USE_BIAS, bool OUT_HALF>
__global__ __launch_bounds__(256) void gemm_f16_kernel(
    const __half* __restrict__ A, const __half* __restrict__ B,
    const float* __restrict__ bias, void* __restrict__ Cv,
    int M, int N, int K)
{
    __shared__ __align__(16) __half As[4][128][24];
    __shared__ __align__(16) __half Bs[4][16][264];

    const int tid  = threadIdx.x;
    const int wid  = tid >> 5;
    const int lane = tid & 31;
    const int warp_m = wid & 1;
    const int warp_n = wid >> 1;         // 0..3
    const int rowBase = blockIdx.y * 128;
    const int colBase = blockIdx.x * 256;
    const int KT = K / 16;

    // staging: A 1 chunk/thread, B 2 chunks/thread (16B each)
    const int ar  = tid >> 1;            // 0..127
    const int ac  = (tid & 1) * 8;       // 0 or 8
    const uint32_t as_base = smem_u32(&As[0][0][0]);
    const uint32_t bs_base = smem_u32(&Bs[0][0][0]);
    const uint32_t a_stage = 128 * 24 * 2;
    const uint32_t b_stage = 16 * 264 * 2;

    const uint32_t a_dst = as_base + (uint32_t)((ar * 24 + ac) * 2);
    const int a_row_ok = (rowBase + ar < M) ? 16 : 0;
    const __half* a_src = A + (size_t)(a_row_ok ? (rowBase + ar) : 0) * K + ac;

    const int br0 = tid >> 5,         bc0 = (tid & 31) * 8;
    const int br1 = (tid + 256) >> 5, bc1 = ((tid + 256) & 31) * 8;
    const uint32_t b_dst0 = bs_base + (uint32_t)((br0 * 264 + bc0) * 2);
    const uint32_t b_dst1 = bs_base + (uint32_t)((br1 * 264 + bc1) * 2);
    const __half* b_src0 = B + (size_t)br0 * N + colBase + bc0;
    const __half* b_src1 = B + (size_t)br1 * N + colBase + bc1;

    auto issue_stage = [&](int s, int t) {
        cp_async16(a_dst + s * a_stage, a_src + t * 16, a_row_ok);
        cp_async16(b_dst0 + s * b_stage, b_src0 + (size_t)t * 16 * N, 16);
        cp_async16(b_dst1 + s * b_stage, b_src1 + (size_t)t * 16 * N, 16);
    };

    float acc[4][8][4];
    #pragma unroll
    for (int i = 0; i < 4; i++)
        #pragma unroll
        for (int j = 0; j < 8; j++)
            #pragma unroll
            for (int r = 0; r < 4; r++) acc[i][j][r] = 0.f;

    // fragment ldmatrix addresses
    uint32_t a_off[4], b_off[8];
    {
        const int arow = lane & 15;
        const int acol = (lane >> 4) * 8;
        #pragma unroll
        for (int i = 0; i < 4; i++)
            a_off[i] = as_base + (uint32_t)(((warp_m * 64 + i * 16 + arow) * 24 + acol) * 2);
        #pragma unroll
        for (int j = 0; j < 8; j++)
            b_off[j] = bs_base + (uint32_t)(((lane & 15) * 264 + warp_n * 64 + j * 8) * 2);
    }

    // prologue: stages 0..2 in flight
    #pragma unroll
    for (int s = 0; s < 3; s++) { issue_stage(s, s); cp_commit(); }

    for (int t = 0; t < KT; t++) {
        cp_wait2();
        __syncthreads();
        if (t + 3 < KT) issue_stage((t + 3) & 3, t + 3);
        cp_commit();

        const int buf = t & 3;
        uint32_t af[4][4];
        #pragma unroll
        for (int i = 0; i < 4; i++) ldmatrix_x4(af[i], a_off[i] + buf * a_stage);

        #pragma unroll
        for (int jb = 0; jb < 2; jb++) {
            uint32_t bf[4][2];
            #pragma unroll
            for (int jj = 0; jj < 4; jj++)
                ldmatrix_x2t(bf[jj], b_off[jb * 4 + jj] + buf * b_stage);
            #pragma unroll
            for (int i = 0; i < 4; i++)
                #pragma unroll
                for (int jj = 0; jj < 4; jj++)
                    mma_f16(acc[i][jb * 4 + jj], af[i], bf[jj]);
        }
    }

    const int lg = lane >> 2;
    const int lr = lane & 3;
    #pragma unroll
    for (int i = 0; i < 4; i++) {
        const int r0 = rowBase + warp_m * 64 + i * 16 + lg;
        #pragma unroll
        for (int half = 0; half < 2; half++) {
            const int rr = r0 + half * 8;
            if (rr >= M) continue;
            #pragma unroll
            for (int j = 0; j < 8; j++) {
                const int cc = colBase + warp_n * 64 + j * 8 + lr * 2;
                float v0 = acc[i][j][half * 2 + 0];
                float v1 = acc[i][j][half * 2 + 1];
                if (USE_BIAS) { v0 += bias[cc]; v1 += bias[cc + 1]; }
                if (OUT_HALF) {
                    __half2* C = (__half2*)Cv;
                    C[((size_t)rr * N + cc) >> 1] = __floats2half2_rn(v0, v1);
                } else {
                    float* C = (float*)Cv;
                    *(float2*)(C + (size_t)rr * N + cc) = make_float2(v0, v1);
                }
            }
        }
    }
}

// ---------------- CSR gather aggregation (fp16 in, fp32 accumulate, fp16 out) ----------------
template <bool L1>
__global__ __launch_bounds__(256) void gather_kernel(
    const __half* __restrict__ srcfeat,
    const float* __restrict__ bias,
    __half* __restrict__ out)
{
    __shared__ float2 se[8][32];
    const int w    = threadIdx.x >> 5;
    const int warp = blockIdx.x * 8 + w;
    const int lane = threadIdx.x & 31;
    if (warp >= N_NODES) return;

    const int start = g_rowptr[warp];
    const int end   = start + g_cnt[warp];
    const float di  = g_dis[warp];
    const float nn  = di * di;

    float acc[8];

    // self term
    {
        uint4 raw = __ldg((const uint4*)(srcfeat + (size_t)warp * MID_DIM) + lane);
        const __half2* hp = (const __half2*)&raw;
        #pragma unroll
        for (int q = 0; q < 4; q++) {
            float2 f = __half22float2(hp[q]);
            acc[2 * q]     = f.x * nn;
            acc[2 * q + 1] = f.y * nn;
        }
    }

    // edges: stage 32 records in smem, LDS broadcast per edge
    for (int base = start; base < end; base += 32) {
        const int rem = min(32, end - base);
        if (base + lane < end) se[w][lane] = __ldg(&g_epack[base + lane]);
        __syncwarp();
        #pragma unroll 4
        for (int j = 0; j < rem; j++) {
            const float2 e = se[w][j];
            const int   s  = __float_as_int(e.x);
            const float wt = e.y;
            uint4 raw = __ldg((const uint4*)(srcfeat + (size_t)s * MID_DIM) + lane);
            const __half2* hp = (const __half2*)&raw;
            #pragma unroll
            for (int q = 0; q < 4; q++) {
                float2 f = __half22float2(hp[q]);
                acc[2 * q]     = fmaf(wt, f.x, acc[2 * q]);
                acc[2 * q + 1] = fmaf(wt, f.y, acc[2 * q + 1]);
            }
        }
        __syncwarp();
    }

    uint4 outv;
    __half2* op = (__half2*)&outv;
    if (L1) {
        const int c8 = lane * 8;
        float4 bb0 = *(const float4*)(bias + c8);
        float4 bb1 = *(const float4*)(bias + c8 + 4);
        float b[8] = {bb0.x, bb0.y, bb0.z, bb0.w, bb1.x, bb1.y, bb1.z, bb1.w};
        #pragma unroll
        for (int q = 0; q < 4; q++) {
            float v0 = fmaxf(acc[2 * q]     + b[2 * q],     0.f);
            float v1 = fmaxf(acc[2 * q + 1] + b[2 * q + 1], 0.f);
            op[q] = __floats2half2_rn(v0, v1);
        }
    } else {
        #pragma unroll
        for (int q = 0; q < 4; q++)
            op[q] = __floats2half2_rn(acc[2 * q], acc[2 * q + 1]);
    }
    ((uint4*)(out + (size_t)warp * MID_DIM))[lane] = outv;
}

// ---------------- launch ----------------
extern "C" void kernel_launch(void* const* d_in, const int* in_sizes, int n_in,
                              void* d_out, int out_size)
{
    const float* x  = (const float*)d_in[0];
    const void*  ei = d_in[1];
    const float* W1 = (const float*)d_in[2];
    const float* b1 = (const float*)d_in[3];
    const float* W2 = (const float*)d_in[4];
    const float* b2 = (const float*)d_in[5];
    float* out = (float*)d_out;

    __half *xh, *w1h, *w2h, *xw, *h, *ag2;
    cudaGetSymbolAddress((void**)&xh,  g_xh);
    cudaGetSymbolAddress((void**)&w1h, g_w1h);
    cudaGetSymbolAddress((void**)&w2h, g_w2h);
    cudaGetSymbolAddress((void**)&xw,  g_xw);
    cudaGetSymbolAddress((void**)&h,   g_h);
    cudaGetSymbolAddress((void**)&ag2, g_ag2);

    const int nb_nodes = (N_NODES + 255) / 256;
    const int nb_edges = (N_EDGES + 255) / 256;
    const int mblocks = (N_NODES + 127) / 128;
    const int gblocks = (N_NODES + 7) / 8;

    // 1-3: fp16 conversions (W1, W2, x)
    {
        int n8w = (IN_DIM * MID_DIM) / 8;
        conv_half_kernel<<<(n8w + 255) / 256, 256>>>((const float4*)W1, (uint4*)w1h, n8w);
        conv_half_kernel<<<(n8w + 255) / 256, 256>>>((const float4*)W2, (uint4*)w2h, n8w);
        int n8x = (N_NODES * IN_DIM) / 8;
        conv_half_kernel<<<(n8x + 255) / 256, 256>>>((const float4*)x, (uint4*)xh, n8x);
    }

    // 4 (ncu capture slot): GEMM1 xw = x@W1 (fp16 out)
    gemm_f16_kernel<false, true><<<dim3(MID_DIM / 256, mblocks), 256>>>(
        xh, w1h, nullptr, xw, N_NODES, MID_DIM, IN_DIM);

    // CSR build (merged: zero+detect; dis folded into scan1)
    zero_detect_kernel<<<nb_nodes, 256>>>((const int*)ei);
    hist_kernel<<<nb_edges, 256>>>(ei);
    scan1_kernel<<<NBLK_SCAN, 256>>>();
    scan2_kernel<<<1, 256>>>();
    scan3_kernel<<<NBLK_SCAN, 256>>>();
    scatter_kernel<<<nb_edges, 256>>>(ei);

    // layer 1 aggregation: h = relu(A_norm xw + b1)
    gather_kernel<true><<<gblocks, 256>>>(xw, b1, h);

    // layer 2: ag2 = A_norm h ; out = ag2@W2 + b2
    gather_kernel<false><<<gblocks, 256>>>(h, nullptr, ag2);
    gemm_f16_kernel<true, false><<<dim3(IN_DIM / 256, mblocks), 256>>>(
        ag2, w2h, b2, out, N_NODES, IN_DIM, MID_DIM);
}

// round 15
// speedup vs baseline: 1.5705x; 1.0437x over previous
#include <cuda_runtime.h>
#include <cuda_fp16.h>
#include <cstdint>

#define N_NODES 50000
#define N_EDGES 1600000
#define IN_DIM  1024
#define MID_DIM 256
#define NBLK_SCAN ((N_NODES + 255) / 256)   // 196

// ---------------- scratch (device globals; no allocs allowed) ----------------
__device__ __align__(16) float  g_dis[N_NODES];
__device__ __align__(16) __half g_xh  [(size_t)N_NODES * IN_DIM];   // fp16(x)
__device__ __align__(16) __half g_w1h [(size_t)IN_DIM * MID_DIM];   // fp16(W1)
__device__ __align__(16) __half g_w2h [(size_t)MID_DIM * IN_DIM];   // fp16(W2)
__device__ __align__(16) __half g_xw  [(size_t)N_NODES * MID_DIM];  // x@W1
__device__ __align__(16) __half g_h   [(size_t)N_NODES * MID_DIM];  // relu(A xw + b1)
__device__ __align__(16) __half g_ag2 [(size_t)N_NODES * MID_DIM];  // A h
__device__ int    g_cnt[N_NODES];      // zeroed by gather2 of the PREVIOUS call (globals start zeroed)
__device__ int    g_rowptr[N_NODES];
__device__ int    g_cur[N_NODES];
__device__ int    g_bsum[NBLK_SCAN];
__device__ __align__(8) float2 g_epack[N_EDGES];  // {src_as_float_bits, norm}
__device__ int    g_is64;

// ---------------- helpers ----------------
__device__ __forceinline__ uint32_t smem_u32(const void* p) {
    uint32_t a;
    asm("{ .reg .u64 t; cvta.to.shared.u64 t, %1; cvt.u32.u64 %0, t; }"
        : "=r"(a) : "l"(p));
    return a;
}
__device__ __forceinline__ void ldmatrix_x4(uint32_t* r, uint32_t addr) {
    asm volatile("ldmatrix.sync.aligned.m8n8.x4.shared.b16 {%0,%1,%2,%3}, [%4];"
                 : "=r"(r[0]), "=r"(r[1]), "=r"(r[2]), "=r"(r[3]) : "r"(addr));
}
__device__ __forceinline__ void ldmatrix_x2t(uint32_t* r, uint32_t addr) {
    asm volatile("ldmatrix.sync.aligned.m8n8.x2.trans.shared.b16 {%0,%1}, [%2];"
                 : "=r"(r[0]), "=r"(r[1]) : "r"(addr));
}
__device__ __forceinline__ void mma_f16(float* c, const uint32_t* a, const uint32_t* b) {
    asm volatile(
        "mma.sync.aligned.m16n8k16.row.col.f32.f16.f16.f32 "
        "{%0,%1,%2,%3}, {%4,%5,%6,%7}, {%8,%9}, {%0,%1,%2,%3};"
        : "+f"(c[0]), "+f"(c[1]), "+f"(c[2]), "+f"(c[3])
        : "r"(a[0]), "r"(a[1]), "r"(a[2]), "r"(a[3]), "r"(b[0]), "r"(b[1]));
}
__device__ __forceinline__ void cp_async16(uint32_t dst, const void* src, int nbytes) {
    asm volatile("cp.async.ca.shared.global [%0], [%1], 16, %2;"
                 :: "r"(dst), "l"(src), "r"(nbytes));
}
__device__ __forceinline__ void cp_commit() {
    asm volatile("cp.async.commit_group;");
}
__device__ __forceinline__ void cp_wait2() {
    asm volatile("cp.async.wait_group 2;");
}

__device__ __forceinline__ int edge_node(const void* ei, long long idx, int is64) {
    if (is64) return (int)((const long long*)ei)[idx];
    return ((const int*)ei)[idx];
}

__device__ __forceinline__ void conv8(const float4* __restrict__ src,
                                      uint4* __restrict__ dst, int i) {
    float4 a = __ldg(src + 2 * i);
    float4 b = __ldg(src + 2 * i + 1);
    uint4 o;
    ((__half2*)&o)[0] = __floats2half2_rn(a.x, a.y);
    ((__half2*)&o)[1] = __floats2half2_rn(a.z, a.w);
    ((__half2*)&o)[2] = __floats2half2_rn(b.x, b.y);
    ((__half2*)&o)[3] = __floats2half2_rn(b.z, b.w);
    dst[i] = o;
}

// ---------------- fused prep: conv_x + conv_W1 + conv_W2 + hist + detect ----------------
// conv_x: 25000 blocks of 256x8 elts (6.4M float8 groups), hist: 6250 blocks (1 edge/thread),
// interleaved 4:1 (bid%5==4 -> hist) so hist L2-atomic work overlaps DRAM-bound conversion.
// Each hist block self-detects the edge dtype via ballot (int64 layout => odd words all zero).
// Requires g_cnt == 0 on entry (maintained by gather2 of the previous call).
#define NB_MAIN 31250                  // 25000 conv_x + 6250 hist
#define NB_W1   (NB_MAIN)              // +128
#define NB_W2   (NB_MAIN + 128)        // +128
#define NB_PREP (NB_MAIN + 256)

__global__ __launch_bounds__(256) void prep_kernel(
    const float4* __restrict__ x,  uint4* __restrict__ xh,
    const float4* __restrict__ W1, uint4* __restrict__ w1h,
    const float4* __restrict__ W2, uint4* __restrict__ w2h,
    const void* __restrict__ ei)
{
    const int bid = blockIdx.x;
    const int tid = threadIdx.x;
    if (bid < NB_MAIN) {
        const int grp = bid / 5, rem = bid % 5;
        if (rem == 4) {
            // hist block grp in [0, 6250)
            const int* ew = (const int*)ei;
            int nz = (ew[2 * tid + 1] != 0);
            int any = __syncthreads_or(nz);
            int is64 = !any;
            if (grp == 0 && tid == 0) g_is64 = is64;   // for scatter (later launch)
            int e = grp * 256 + tid;                    // < 1.6M exactly
            int d = edge_node(ei, (long long)e + N_EDGES, is64);
            atomicAdd(&g_cnt[d], 1);
        } else {
            int cb = grp * 4 + rem;                     // conv_x block in [0, 25000)
            conv8(x, xh, cb * 256 + tid);
        }
    } else if (bid < NB_W2) {
        conv8(W1, w1h, (bid - NB_W1) * 256 + tid);
    } else {
        conv8(W2, w2h, (bid - NB_W2) * 256 + tid);
    }
}

// ---------------- CSR scans ----------------
// blockwise inclusive scan of g_cnt -> g_rowptr, block totals -> g_bsum; also g_dis
__global__ void scan1_kernel() {
    __shared__ int sh[256];
    int i = blockIdx.x * 256 + threadIdx.x;
    int v = (i < N_NODES) ? g_cnt[i] : 0;
    if (i < N_NODES) g_dis[i] = rsqrtf((float)(v + 1));   // +1 self loop
    sh[threadIdx.x] = v;
    __syncthreads();
    #pragma unroll
    for (int off = 1; off < 256; off <<= 1) {
        int t = (threadIdx.x >= off) ? sh[threadIdx.x - off] : 0;
        __syncthreads();
        sh[threadIdx.x] += t;
        __syncthreads();
    }
    if (i < N_NODES) g_rowptr[i] = sh[threadIdx.x];
    if (threadIdx.x == 255) g_bsum[blockIdx.x] = sh[255];
}
// merged scan2+scan3: each block locally re-scans the 196 block sums (read-only),
// then converts its nodes to exclusive offsets and inits cursors.
__global__ void scan23_kernel() {
    __shared__ int sh[256];
    const int t = threadIdx.x;
    sh[t] = (t < NBLK_SCAN) ? g_bsum[t] : 0;
    __syncthreads();
    #pragma unroll
    for (int off = 1; off < 256; off <<= 1) {
        int u = (t >= off) ? sh[t - off] : 0;
        __syncthreads();
        sh[t] += u;
        __syncthreads();
    }
    const int blockOff = (blockIdx.x == 0) ? 0 : sh[blockIdx.x - 1];
    int i = blockIdx.x * 256 + t;
    if (i < N_NODES) {
        int ex = g_rowptr[i] - g_cnt[i] + blockOff;
        g_rowptr[i] = ex;
        g_cur[i] = ex;
    }
}
__global__ void scatter_kernel(const void* __restrict__ ei) {
    int e = blockIdx.x * blockDim.x + threadIdx.x;
    if (e >= N_EDGES) return;
    int is64 = g_is64;
    int s = edge_node(ei, e, is64);
    int d = edge_node(ei, (long long)e + N_EDGES, is64);
    int pos = atomicAdd(&g_cur[d], 1);
    g_epack[pos] = make_float2(__int_as_float(s), g_dis[s] * g_dis[d]);
}

// ---------------- fp16 mma.sync GEMM, BM=128 BN=256 BK=16, cp.async 4-stage ----------------
// (R9 schedule — empirically best: 85us on GEMM1, tensor ~50%. DO NOT TOUCH.)
template <bool USE_BIAS, bool OUT_HALF>
__global__ __launch_bounds__(256) void gemm_f16_kernel(
    const __half* __restrict__ A, const __half* __restrict__ B,
    const float* __restrict__ bias, void* __restrict__ Cv,
    int M, int N, int K)
{
    __shared__ __align__(16) __half As[4][128][24];
    __shared__ __align__(16) __half Bs[4][16][264];

    const int tid  = threadIdx.x;
    const int wid  = tid >> 5;
    const int lane = tid & 31;
    const int warp_m = wid & 1;
    const int warp_n = wid >> 1;         // 0..3
    const int rowBase = blockIdx.y * 128;
    const int colBase = blockIdx.x * 256;
    const int KT = K / 16;

    const int ar  = tid >> 1;            // 0..127
    const int ac  = (tid & 1) * 8;       // 0 or 8
    const uint32_t as_base = smem_u32(&As[0][0][0]);
    const uint32_t bs_base = smem_u32(&Bs[0][0][0]);
    const uint32_t a_stage = 128 * 24 * 2;
    const uint32_t b_stage = 16 * 264 * 2;

    const uint32_t a_dst = as_base + (uint32_t)((ar * 24 + ac) * 2);
    const int a_row_ok = (rowBase + ar < M) ? 16 : 0;
    const __half* a_src = A + (size_t)(a_row_ok ? (rowBase + ar) : 0) * K + ac;

    const int br0 = tid >> 5,         bc0 = (tid & 31) * 8;
    const int br1 = (tid + 256) >> 5, bc1 = ((tid + 256) & 31) * 8;
    const uint32_t b_dst0 = bs_base + (uint32_t)((br0 * 264 + bc0) * 2);
    const uint32_t b_dst1 = bs_base + (uint32_t)((br1 * 264 + bc1) * 2);
    const __half* b_src0 = B + (size_t)br0 * N + colBase + bc0;
    const __half* b_src1 = B + (size_t)br1 * N + colBase + bc1;

    auto issue_stage = [&](int s, int t) {
        cp_async16(a_dst + s * a_stage, a_src + t * 16, a_row_ok);
        cp_async16(b_dst0 + s * b_stage, b_src0 + (size_t)t * 16 * N, 16);
        cp_async16(b_dst1 + s * b_stage, b_src1 + (size_t)t * 16 * N, 16);
    };

    float acc[4][8][4];
    #pragma unroll
    for (int i = 0; i < 4; i++)
        #pragma unroll
        for (int j = 0; j < 8; j++)
            #pragma unroll
            for (int r = 0; r < 4; r++) acc[i][j][r] = 0.f;

    uint32_t a_off[4], b_off[8];
    {
        const int arow = lane & 15;
        const int acol = (lane >> 4) * 8;
        #pragma unroll
        for (int i = 0; i < 4; i++)
            a_off[i] = as_base + (uint32_t)(((warp_m * 64 + i * 16 + arow) * 24 + acol) * 2);
        #pragma unroll
        for (int j = 0; j < 8; j++)
            b_off[j] = bs_base + (uint32_t)(((lane & 15) * 264 + warp_n * 64 + j * 8) * 2);
    }

    #pragma unroll
    for (int s = 0; s < 3; s++) { issue_stage(s, s); cp_commit(); }

    for (int t = 0; t < KT; t++) {
        cp_wait2();
        __syncthreads();
        if (t + 3 < KT) issue_stage((t + 3) & 3, t + 3);
        cp_commit();

        const int buf = t & 3;
        uint32_t af[4][4];
        #pragma unroll
        for (int i = 0; i < 4; i++) ldmatrix_x4(af[i], a_off[i] + buf * a_stage);

        #pragma unroll
        for (int jb = 0; jb < 2; jb++) {
            uint32_t bf[4][2];
            #pragma unroll
            for (int jj = 0; jj < 4; jj++)
                ldmatrix_x2t(bf[jj], b_off[jb * 4 + jj] + buf * b_stage);
            #pragma unroll
            for (int i = 0; i < 4; i++)
                #pragma unroll
                for (int jj = 0; jj < 4; jj++)
                    mma_f16(acc[i][jb * 4 + jj], af[i], bf[jj]);
        }
    }

    const int lg = lane >> 2;
    const int lr = lane & 3;
    #pragma unroll
    for (int i = 0; i < 4; i++) {
        const int r0 = rowBase + warp_m * 64 + i * 16 + lg;
        #pragma unroll
        for (int half = 0; half < 2; half++) {
            const int rr = r0 + half * 8;
            if (rr >= M) continue;
            #pragma unroll
            for (int j = 0; j < 8; j++) {
                const int cc = colBase + warp_n * 64 + j * 8 + lr * 2;
                float v0 = acc[i][j][half * 2 + 0];
                float v1 = acc[i][j][half * 2 + 1];
                if (USE_BIAS) { v0 += bias[cc]; v1 += bias[cc + 1]; }
                if (OUT_HALF) {
                    __half2* C = (__half2*)Cv;
                    C[((size_t)rr * N + cc) >> 1] = __floats2half2_rn(v0, v1);
                } else {
                    float* C = (float*)Cv;
                    *(float2*)(C + (size_t)rr * N + cc) = make_float2(v0, v1);
                }
            }
        }
    }
}

// ---------------- CSR gather aggregation (fp16 in, fp32 accumulate, fp16 out) ----------------
// L1: out = relu(agg + b1).  L2 (!L1): out = agg; also zeroes g_cnt for the NEXT call.
template <bool L1>
__global__ __launch_bounds__(256) void gather_kernel(
    const __half* __restrict__ srcfeat,
    const float* __restrict__ bias,
    __half* __restrict__ out)
{
    __shared__ float2 se[8][32];
    const int w    = threadIdx.x >> 5;
    const int warp = blockIdx.x * 8 + w;
    const int lane = threadIdx.x & 31;
    if (warp >= N_NODES) return;

    const int start = g_rowptr[warp];
    const int end   = start + g_cnt[warp];
    const float di  = g_dis[warp];
    const float nn  = di * di;

    float acc[8];

    // self term
    {
        uint4 raw = __ldg((const uint4*)(srcfeat + (size_t)warp * MID_DIM) + lane);
        const __half2* hp = (const __half2*)&raw;
        #pragma unroll
        for (int q = 0; q < 4; q++) {
            float2 f = __half22float2(hp[q]);
            acc[2 * q]     = f.x * nn;
            acc[2 * q + 1] = f.y * nn;
        }
    }

    // edges: stage 32 records in smem, LDS broadcast per edge
    for (int base = start; base < end; base += 32) {
        const int rem = min(32, end - base);
        if (base + lane < end) se[w][lane] = __ldg(&g_epack[base + lane]);
        __syncwarp();
        #pragma unroll 4
        for (int j = 0; j < rem; j++) {
            const float2 e = se[w][j];
            const int   s  = __float_as_int(e.x);
            const float wt = e.y;
            uint4 raw = __ldg((const uint4*)(srcfeat + (size_t)s * MID_DIM) + lane);
            const __half2* hp = (const __half2*)&raw;
            #pragma unroll
            for (int q = 0; q < 4; q++) {
                float2 f = __half22float2(hp[q]);
                acc[2 * q]     = fmaf(wt, f.x, acc[2 * q]);
                acc[2 * q + 1] = fmaf(wt, f.y, acc[2 * q + 1]);
            }
        }
        __syncwarp();
    }

    uint4 outv;
    __half2* op = (__half2*)&outv;
    if (L1) {
        const int c8 = lane * 8;
        float4 bb0 = *(const float4*)(bias + c8);
        float4 bb1 = *(const float4*)(bias + c8 + 4);
        float b[8] = {bb0.x, bb0.y, bb0.z, bb0.w, bb1.x, bb1.y, bb1.z, bb1.w};
        #pragma unroll
        for (int q = 0; q < 4; q++) {
            float v0 = fmaxf(acc[2 * q]     + b[2 * q],     0.f);
            float v1 = fmaxf(acc[2 * q + 1] + b[2 * q + 1], 0.f);
            op[q] = __floats2half2_rn(v0, v1);
        }
    } else {
        #pragma unroll
        for (int q = 0; q < 4; q++)
            op[q] = __floats2half2_rn(acc[2 * q], acc[2 * q + 1]);
    }
    ((uint4*)(out + (size_t)warp * MID_DIM))[lane] = outv;

    // last reader of g_cnt resets it for the next kernel_launch call
    if (!L1 && lane == 0) g_cnt[warp] = 0;
}

// ---------------- launch ----------------
extern "C" void kernel_launch(void* const* d_in, const int* in_sizes, int n_in,
                              void* d_out, int out_size)
{
    const float* x  = (const float*)d_in[0];
    const void*  ei = d_in[1];
    const float* W1 = (const float*)d_in[2];
    const float* b1 = (const float*)d_in[3];
    const float* W2 = (const float*)d_in[4];
    const float* b2 = (const float*)d_in[5];
    float* out = (float*)d_out;

    __half *xh, *w1h, *w2h, *xw, *h, *ag2;
    cudaGetSymbolAddress((void**)&xh,  g_xh);
    cudaGetSymbolAddress((void**)&w1h, g_w1h);
    cudaGetSymbolAddress((void**)&w2h, g_w2h);
    cudaGetSymbolAddress((void**)&xw,  g_xw);
    cudaGetSymbolAddress((void**)&h,   g_h);
    cudaGetSymbolAddress((void**)&ag2, g_ag2);

    const int nb_edges = (N_EDGES + 255) / 256;
    const int mblocks = (N_NODES + 127) / 128;
    const int gblocks = (N_NODES + 7) / 8;

    // 1. fused prep: conv x/W1/W2 -> fp16, hist (interleaved), dtype detect
    prep_kernel<<<NB_PREP, 256>>>((const float4*)x,  (uint4*)xh,
                                  (const float4*)W1, (uint4*)w1h,
                                  (const float4*)W2, (uint4*)w2h, ei);

    // 2. GEMM1: xw = x@W1 (fp16 out)
    gemm_f16_kernel<false, true><<<dim3(MID_DIM / 256, mblocks), 256>>>(
        xh, w1h, nullptr, xw, N_NODES, MID_DIM, IN_DIM);

    // 3-5. CSR: scan1 (incl. dis), merged scan2+3, scatter
    scan1_kernel<<<NBLK_SCAN, 256>>>();
    scan23_kernel<<<NBLK_SCAN, 256>>>();
    scatter_kernel<<<nb_edges, 256>>>(ei);

    // 6. layer 1 aggregation: h = relu(A_norm xw + b1)
    gather_kernel<true><<<gblocks, 256>>>(xw, b1, h);

    // 7. layer 2 aggregation: ag2 = A_norm h (+ reset g_cnt)
    gather_kernel<false><<<gblocks, 256>>>(h, nullptr, ag2);

    // 8. GEMM2: out = ag2@W2 + b2
    gemm_f16_kernel<true, false><<<dim3(IN_DIM / 256, mblocks), 256>>>(
        ag2, w2h, b2, out, N_NODES, IN_DIM, MID_DIM);
}

// round 17
// speedup vs baseline: 1.6543x; 1.0534x over previous
#include <cuda_runtime.h>
#include <cuda_fp16.h>
#include <cstdint>

#define N_NODES 50000
#define N_EDGES 1600000
#define IN_DIM  1024
#define MID_DIM 256
#define NBLK_SCAN ((N_NODES + 255) / 256)   // 196

// ---------------- scratch (device globals; no allocs allowed) ----------------
__device__ __align__(16) float  g_dis[N_NODES];
__device__ __align__(16) __half g_xh  [(size_t)N_NODES * IN_DIM];   // fp16(x)
__device__ __align__(16) __half g_w1h [(size_t)IN_DIM * MID_DIM];   // fp16(W1)
__device__ __align__(16) __half g_w2h [(size_t)MID_DIM * IN_DIM];   // fp16(W2)
__device__ __align__(16) __half g_xw  [(size_t)N_NODES * MID_DIM];  // x@W1
__device__ __align__(16) __half g_h   [(size_t)N_NODES * MID_DIM];  // relu(A xw + b1)
__device__ __align__(16) __half g_ag2 [(size_t)N_NODES * MID_DIM];  // A h
__device__ int    g_cnt[N_NODES];      // zeroed by gather2 of the PREVIOUS call (globals start zeroed)
__device__ int    g_rowptr[N_NODES];
__device__ int    g_cur[N_NODES];
__device__ int    g_bsum[NBLK_SCAN];
__device__ __align__(8) float2 g_epack[N_EDGES];  // {src_as_float_bits, norm}
__device__ int    g_is64;

// ---------------- helpers ----------------
__device__ __forceinline__ uint32_t smem_u32(const void* p) {
    uint32_t a;
    asm("{ .reg .u64 t; cvta.to.shared.u64 t, %1; cvt.u32.u64 %0, t; }"
        : "=r"(a) : "l"(p));
    return a;
}
__device__ __forceinline__ void ldmatrix_x4(uint32_t* r, uint32_t addr) {
    asm volatile("ldmatrix.sync.aligned.m8n8.x4.shared.b16 {%0,%1,%2,%3}, [%4];"
                 : "=r"(r[0]), "=r"(r[1]), "=r"(r[2]), "=r"(r[3]) : "r"(addr));
}
__device__ __forceinline__ void ldmatrix_x2t(uint32_t* r, uint32_t addr) {
    asm volatile("ldmatrix.sync.aligned.m8n8.x2.trans.shared.b16 {%0,%1}, [%2];"
                 : "=r"(r[0]), "=r"(r[1]) : "r"(addr));
}
__device__ __forceinline__ void mma_f16(float* c, const uint32_t* a, const uint32_t* b) {
    asm volatile(
        "mma.sync.aligned.m16n8k16.row.col.f32.f16.f16.f32 "
        "{%0,%1,%2,%3}, {%4,%5,%6,%7}, {%8,%9}, {%0,%1,%2,%3};"
        : "+f"(c[0]), "+f"(c[1]), "+f"(c[2]), "+f"(c[3])
        : "r"(a[0]), "r"(a[1]), "r"(a[2]), "r"(a[3]), "r"(b[0]), "r"(b[1]));
}
__device__ __forceinline__ void cp_async16(uint32_t dst, const void* src, int nbytes) {
    asm volatile("cp.async.ca.shared.global [%0], [%1], 16, %2;"
                 :: "r"(dst), "l"(src), "r"(nbytes));
}
__device__ __forceinline__ void cp_commit() {
    asm volatile("cp.async.commit_group;");
}
__device__ __forceinline__ void cp_wait2() {
    asm volatile("cp.async.wait_group 2;");
}

__device__ __forceinline__ int edge_node(const void* ei, long long idx, int is64) {
    if (is64) return (int)((const long long*)ei)[idx];
    return ((const int*)ei)[idx];
}

__device__ __forceinline__ void conv8(const float4* __restrict__ src,
                                      uint4* __restrict__ dst, int i) {
    float4 a = __ldg(src + 2 * i);
    float4 b = __ldg(src + 2 * i + 1);
    uint4 o;
    ((__half2*)&o)[0] = __floats2half2_rn(a.x, a.y);
    ((__half2*)&o)[1] = __floats2half2_rn(a.z, a.w);
    ((__half2*)&o)[2] = __floats2half2_rn(b.x, b.y);
    ((__half2*)&o)[3] = __floats2half2_rn(b.z, b.w);
    dst[i] = o;
}

// ---------------- fused prep: conv_x + conv_W1 + conv_W2 + hist + detect ----------------
#define NB_MAIN 31250                  // 25000 conv_x + 6250 hist
#define NB_W1   (NB_MAIN)              // +128
#define NB_W2   (NB_MAIN + 128)        // +128
#define NB_PREP (NB_MAIN + 256)

__global__ __launch_bounds__(256) void prep_kernel(
    const float4* __restrict__ x,  uint4* __restrict__ xh,
    const float4* __restrict__ W1, uint4* __restrict__ w1h,
    const float4* __restrict__ W2, uint4* __restrict__ w2h,
    const void* __restrict__ ei)
{
    const int bid = blockIdx.x;
    const int tid = threadIdx.x;
    if (bid < NB_MAIN) {
        const int grp = bid / 5, rem = bid % 5;
        if (rem == 4) {
            // hist block grp in [0, 6250)
            const int* ew = (const int*)ei;
            int nz = (ew[2 * tid + 1] != 0);
            int any = __syncthreads_or(nz);
            int is64 = !any;
            if (grp == 0 && tid == 0) g_is64 = is64;   // for scatter (later launch)
            int e = grp * 256 + tid;                    // < 1.6M exactly
            int d = edge_node(ei, (long long)e + N_EDGES, is64);
            atomicAdd(&g_cnt[d], 1);
        } else {
            int cb = grp * 4 + rem;                     // conv_x block in [0, 25000)
            conv8(x, xh, cb * 256 + tid);
        }
    } else if (bid < NB_W2) {
        conv8(W1, w1h, (bid - NB_W1) * 256 + tid);
    } else {
        conv8(W2, w2h, (bid - NB_W2) * 256 + tid);
    }
}

// ---------------- CSR scans ----------------
__global__ void scan1_kernel() {
    __shared__ int sh[256];
    int i = blockIdx.x * 256 + threadIdx.x;
    int v = (i < N_NODES) ? g_cnt[i] : 0;
    if (i < N_NODES) g_dis[i] = rsqrtf((float)(v + 1));   // +1 self loop
    sh[threadIdx.x] = v;
    __syncthreads();
    #pragma unroll
    for (int off = 1; off < 256; off <<= 1) {
        int t = (threadIdx.x >= off) ? sh[threadIdx.x - off] : 0;
        __syncthreads();
        sh[threadIdx.x] += t;
        __syncthreads();
    }
    if (i < N_NODES) g_rowptr[i] = sh[threadIdx.x];
    if (threadIdx.x == 255) g_bsum[blockIdx.x] = sh[255];
}
__global__ void scan23_kernel() {
    __shared__ int sh[256];
    const int t = threadIdx.x;
    sh[t] = (t < NBLK_SCAN) ? g_bsum[t] : 0;
    __syncthreads();
    #pragma unroll
    for (int off = 1; off < 256; off <<= 1) {
        int u = (t >= off) ? sh[t - off] : 0;
        __syncthreads();
        sh[t] += u;
        __syncthreads();
    }
    const int blockOff = (blockIdx.x == 0) ? 0 : sh[blockIdx.x - 1];
    int i = blockIdx.x * 256 + t;
    if (i < N_NODES) {
        int ex = g_rowptr[i] - g_cnt[i] + blockOff;
        g_rowptr[i] = ex;
        g_cur[i] = ex;
    }
}
__global__ void scatter_kernel(const void* __restrict__ ei) {
    int e = blockIdx.x * blockDim.x + threadIdx.x;
    if (e >= N_EDGES) return;
    int is64 = g_is64;
    int s = edge_node(ei, e, is64);
    int d = edge_node(ei, (long long)e + N_EDGES, is64);
    int pos = atomicAdd(&g_cur[d], 1);
    g_epack[pos] = make_float2(__int_as_float(s), g_dis[s] * g_dis[d]);
}

// ---------------- fp16 mma.sync GEMM, BM=128 BN=256 BK=16, cp.async 4-stage ----------------
// (R9 schedule — empirically best: 85us on GEMM1, tensor ~50%. DO NOT TOUCH.)
template <bool USE_BIAS, bool OUT_HALF>
__global__ __launch_bounds__(256) void gemm_f16_kernel(
    const __half* __restrict__ A, const __half* __restrict__ B,
    const float* __restrict__ bias, void* __restrict__ Cv,
    int M, int N, int K)
{
    __shared__ __align__(16) __half As[4][128][24];
    __shared__ __align__(16) __half Bs[4][16][264];

    const int tid  = threadIdx.x;
    const int wid  = tid >> 5;
    const int lane = tid & 31;
    const int warp_m = wid & 1;
    const int warp_n = wid >> 1;         // 0..3
    const int rowBase = blockIdx.y * 128;
    const int colBase = blockIdx.x * 256;
    const int KT = K / 16;

    const int ar  = tid >> 1;            // 0..127
    const int ac  = (tid & 1) * 8;       // 0 or 8
    const uint32_t as_base = smem_u32(&As[0][0][0]);
    const uint32_t bs_base = smem_u32(&Bs[0][0][0]);
    const uint32_t a_stage = 128 * 24 * 2;
    const uint32_t b_stage = 16 * 264 * 2;

    const uint32_t a_dst = as_base + (uint32_t)((ar * 24 + ac) * 2);
    const int a_row_ok = (rowBase + ar < M) ? 16 : 0;
    const __half* a_src = A + (size_t)(a_row_ok ? (rowBase + ar) : 0) * K + ac;

    const int br0 = tid >> 5,         bc0 = (tid & 31) * 8;
    const int br1 = (tid + 256) >> 5, bc1 = ((tid + 256) & 31) * 8;
    const uint32_t b_dst0 = bs_base + (uint32_t)((br0 * 264 + bc0) * 2);
    const uint32_t b_dst1 = bs_base + (uint32_t)((br1 * 264 + bc1) * 2);
    const __half* b_src0 = B + (size_t)br0 * N + colBase + bc0;
    const __half* b_src1 = B + (size_t)br1 * N + colBase + bc1;

    auto issue_stage = [&](int s, int t) {
        cp_async16(a_dst + s * a_stage, a_src + t * 16, a_row_ok);
        cp_async16(b_dst0 + s * b_stage, b_src0 + (size_t)t * 16 * N, 16);
        cp_async16(b_dst1 + s * b_stage, b_src1 + (size_t)t * 16 * N, 16);
    };

    float acc[4][8][4];
    #pragma unroll
    for (int i = 0; i < 4; i++)
        #pragma unroll
        for (int j = 0; j < 8; j++)
            #pragma unroll
            for (int r = 0; r < 4; r++) acc[i][j][r] = 0.f;

    uint32_t a_off[4], b_off[8];
    {
        const int arow = lane & 15;
        const int acol = (lane >> 4) * 8;
        #pragma unroll
        for (int i = 0; i < 4; i++)
            a_off[i] = as_base + (uint32_t)(((warp_m * 64 + i * 16 + arow) * 24 + acol) * 2);
        #pragma unroll
        for (int j = 0; j < 8; j++)
            b_off[j] = bs_base + (uint32_t)(((lane & 15) * 264 + warp_n * 64 + j * 8) * 2);
    }

    #pragma unroll
    for (int s = 0; s < 3; s++) { issue_stage(s, s); cp_commit(); }

    for (int t = 0; t < KT; t++) {
        cp_wait2();
        __syncthreads();
        if (t + 3 < KT) issue_stage((t + 3) & 3, t + 3);
        cp_commit();

        const int buf = t & 3;
        uint32_t af[4][4];
        #pragma unroll
        for (int i = 0; i < 4; i++) ldmatrix_x4(af[i], a_off[i] + buf * a_stage);

        #pragma unroll
        for (int jb = 0; jb < 2; jb++) {
            uint32_t bf[4][2];
            #pragma unroll
            for (int jj = 0; jj < 4; jj++)
                ldmatrix_x2t(bf[jj], b_off[jb * 4 + jj] + buf * b_stage);
            #pragma unroll
            for (int i = 0; i < 4; i++)
                #pragma unroll
                for (int jj = 0; jj < 4; jj++)
                    mma_f16(acc[i][jb * 4 + jj], af[i], bf[jj]);
        }
    }

    const int lg = lane >> 2;
    const int lr = lane & 3;
    #pragma unroll
    for (int i = 0; i < 4; i++) {
        const int r0 = rowBase + warp_m * 64 + i * 16 + lg;
        #pragma unroll
        for (int half = 0; half < 2; half++) {
            const int rr = r0 + half * 8;
            if (rr >= M) continue;
            #pragma unroll
            for (int j = 0; j < 8; j++) {
                const int cc = colBase + warp_n * 64 + j * 8 + lr * 2;
                float v0 = acc[i][j][half * 2 + 0];
                float v1 = acc[i][j][half * 2 + 1];
                if (USE_BIAS) { v0 += bias[cc]; v1 += bias[cc + 1]; }
                if (OUT_HALF) {
                    __half2* C = (__half2*)Cv;
                    C[((size_t)rr * N + cc) >> 1] = __floats2half2_rn(v0, v1);
                } else {
                    float* C = (float*)Cv;
                    *(float2*)(C + (size_t)rr * N + cc) = make_float2(v0, v1);
                }
            }
        }
    }
}

// ---------------- CSR gather aggregation (fp16 in, fp32 accumulate, fp16 out) ----------------
// L1: out = relu(agg + b1).  L2 (!L1): out = agg; also zeroes g_cnt for the NEXT call.
template <bool L1>
__global__ __launch_bounds__(256) void gather_kernel(
    const __half* __restrict__ srcfeat,
    const float* __restrict__ bias,
    __half* __restrict__ out)
{
    __shared__ float2 se[8][32];
    const int w    = threadIdx.x >> 5;
    const int warp = blockIdx.x * 8 + w;
    const int lane = threadIdx.x & 31;
    if (warp >= N_NODES) return;

    const int start = g_rowptr[warp];
    const int end   = start + g_cnt[warp];
    const float di  = g_dis[warp];
    const float nn  = di * di;

    float acc[8];

    // self term
    {
        uint4 raw = __ldg((const uint4*)(srcfeat + (size_t)warp * MID_DIM) + lane);
        const __half2* hp = (const __half2*)&raw;
        #pragma unroll
        for (int q = 0; q < 4; q++) {
            float2 f = __half22float2(hp[q]);
            acc[2 * q]     = f.x * nn;
            acc[2 * q + 1] = f.y * nn;
        }
    }

    // edges: stage 32 records in smem, LDS broadcast per edge
    for (int base = start; base < end; base += 32) {
        const int rem = min(32, end - base);
        if (base + lane < end) se[w][lane] = __ldg(&g_epack[base + lane]);
        __syncwarp();
        #pragma unroll 4
        for (int j = 0; j < rem; j++) {
            const float2 e = se[w][j];
            const int   s  = __float_as_int(e.x);
            const float wt = e.y;
            uint4 raw = __ldg((const uint4*)(srcfeat + (size_t)s * MID_DIM) + lane);
            const __half2* hp = (const __half2*)&raw;
            #pragma unroll
            for (int q = 0; q < 4; q++) {
                float2 f = __half22float2(hp[q]);
                acc[2 * q]     = fmaf(wt, f.x, acc[2 * q]);
                acc[2 * q + 1] = fmaf(wt, f.y, acc[2 * q + 1]);
            }
        }
        __syncwarp();
    }

    uint4 outv;
    __half2* op = (__half2*)&outv;
    if (L1) {
        const int c8 = lane * 8;
        float4 bb0 = *(const float4*)(bias + c8);
        float4 bb1 = *(const float4*)(bias + c8 + 4);
        float b[8] = {bb0.x, bb0.y, bb0.z, bb0.w, bb1.x, bb1.y, bb1.z, bb1.w};
        #pragma unroll
        for (int q = 0; q < 4; q++) {
            float v0 = fmaxf(acc[2 * q]     + b[2 * q],     0.f);
            float v1 = fmaxf(acc[2 * q + 1] + b[2 * q + 1], 0.f);
            op[q] = __floats2half2_rn(v0, v1);
        }
    } else {
        #pragma unroll
        for (int q = 0; q < 4; q++)
            op[q] = __floats2half2_rn(acc[2 * q], acc[2 * q + 1]);
    }
    ((uint4*)(out + (size_t)warp * MID_DIM))[lane] = outv;

    // last reader of g_cnt resets it for the next kernel_launch call
    if (!L1 && lane == 0) g_cnt[warp] = 0;
}

// ---------------- launch ----------------
extern "C" void kernel_launch(void* const* d_in, const int* in_sizes, int n_in,
                              void* d_out, int out_size)
{
    const float* x  = (const float*)d_in[0];
    const void*  ei = d_in[1];
    const float* W1 = (const float*)d_in[2];
    const float* b1 = (const float*)d_in[3];
    const float* W2 = (const float*)d_in[4];
    const float* b2 = (const float*)d_in[5];
    float* out = (float*)d_out;

    __half *xh, *w1h, *w2h, *xw, *h, *ag2;
    cudaGetSymbolAddress((void**)&xh,  g_xh);
    cudaGetSymbolAddress((void**)&w1h, g_w1h);
    cudaGetSymbolAddress((void**)&w2h, g_w2h);
    cudaGetSymbolAddress((void**)&xw,  g_xw);
    cudaGetSymbolAddress((void**)&h,   g_h);
    cudaGetSymbolAddress((void**)&ag2, g_ag2);

    // persistent side stream + fork/join events (host plumbing only; created once,
    // outside capture — the captured device work is identical on every call)
    static cudaStream_t s_side = nullptr;
    static cudaEvent_t  s_fork = nullptr, s_join = nullptr;
    if (s_side == nullptr) {
        cudaStreamCreateWithFlags(&s_side, cudaStreamNonBlocking);
        cudaEventCreateWithFlags(&s_fork, cudaEventDisableTiming);
        cudaEventCreateWithFlags(&s_join, cudaEventDisableTiming);
    }

    const int nb_edges = (N_EDGES + 255) / 256;
    const int mblocks = (N_NODES + 127) / 128;
    const int gblocks = (N_NODES + 7) / 8;

    // 1. fused prep: conv x/W1/W2 -> fp16, hist (interleaved), dtype detect
    prep_kernel<<<NB_PREP, 256>>>((const float4*)x,  (uint4*)xh,
                                  (const float4*)W1, (uint4*)w1h,
                                  (const float4*)W2, (uint4*)w2h, ei);

    // fork: CSR chain on side stream, concurrent with GEMM1
    cudaEventRecord(s_fork, 0);
    cudaStreamWaitEvent(s_side, s_fork, 0);
    scan1_kernel<<<NBLK_SCAN, 256, 0, s_side>>>();
    scan23_kernel<<<NBLK_SCAN, 256, 0, s_side>>>();
    scatter_kernel<<<nb_edges, 256, 0, s_side>>>(ei);
    cudaEventRecord(s_join, s_side);

    // 2. GEMM1 on main stream (overlaps the CSR branch)
    gemm_f16_kernel<false, true><<<dim3(MID_DIM / 256, mblocks), 256>>>(
        xh, w1h, nullptr, xw, N_NODES, MID_DIM, IN_DIM);

    // join: gather1 needs both GEMM1 (xw) and scatter (epack/rowptr/dis)
    cudaStreamWaitEvent(0, s_join, 0);

    // 3. layer 1 aggregation: h = relu(A_norm xw + b1)
    gather_kernel<true><<<gblocks, 256>>>(xw, b1, h);

    // 4. layer 2 aggregation: ag2 = A_norm h (+ reset g_cnt)
    gather_kernel<false><<<gblocks, 256>>>(h, nullptr, ag2);

    // 5. GEMM2: out = ag2@W2 + b2
    gemm_f16_kernel<true, false><<<dim3(IN_DIM / 256, mblocks), 256>>>(
        ag2, w2h, b2, out, N_NODES, IN_DIM, MID_DIM);
}